// round 10
// baseline (speedup 1.0000x reference)
#include <cuda_runtime.h>
#include <cuda_bf16.h>
#include <cstdint>
#include <math.h>

#define NB 4
#define NW 2048
#define DM 1024
#define NH 16
#define DK 64
#define MT (NB*NW)
#define MWPR (NW/32)

// ---------------- device scratch ----------------
__device__ unsigned g_mb[NB*NW*MWPR];
__device__ __nv_bfloat16 g_xh[3u*MT*DM];   // hi of Q,K,V inputs (slot 0 reused for attn out)
__device__ __nv_bfloat16 g_xl[3u*MT*DM];
__device__ __nv_bfloat16 g_wh[4u*DM*DM];
__device__ __nv_bfloat16 g_wl[4u*DM*DM];
__device__ __nv_bfloat16 g_qh[NB*NH*NW*DK];
__device__ __nv_bfloat16 g_ql[NB*NH*NW*DK];
__device__ __nv_bfloat16 g_kh[NB*NH*NW*DK];
__device__ __nv_bfloat16 g_kl[NB*NH*NW*DK];
__device__ __nv_bfloat16 g_vh[NB*NH*NW*DK];
__device__ __nv_bfloat16 g_vl[NB*NH*NW*DK];

// ---------------- PTX helpers ----------------
__device__ __forceinline__ uint32_t smem_u32(const void* p) {
    uint32_t a;
    asm("{ .reg .u64 t; cvta.to.shared.u64 t, %1; cvt.u32.u64 %0, t; }" : "=r"(a) : "l"(p));
    return a;
}
#define CP_ASYNC16(sa, g) \
    asm volatile("cp.async.cg.shared.global [%0], [%1], 16;" :: "r"(sa), "l"(g))
#define CP_COMMIT() asm volatile("cp.async.commit_group;" ::: "memory")
#define CP_WAIT1()  asm volatile("cp.async.wait_group 1;" ::: "memory")
#define CP_WAIT0()  asm volatile("cp.async.wait_group 0;" ::: "memory")

#define LDSM4(r, addr) \
    asm volatile("ldmatrix.sync.aligned.m8n8.x4.shared.b16 {%0,%1,%2,%3}, [%4];" \
        : "=r"((r)[0]), "=r"((r)[1]), "=r"((r)[2]), "=r"((r)[3]) : "r"(addr))
#define LDSM4T(r, addr) \
    asm volatile("ldmatrix.sync.aligned.m8n8.x4.trans.shared.b16 {%0,%1,%2,%3}, [%4];" \
        : "=r"((r)[0]), "=r"((r)[1]), "=r"((r)[2]), "=r"((r)[3]) : "r"(addr))

#define MMA16816(d, a, b0, b1) \
    asm volatile("mma.sync.aligned.m16n8k16.row.col.f32.bf16.bf16.f32 " \
        "{%0,%1,%2,%3}, {%4,%5,%6,%7}, {%8,%9}, {%0,%1,%2,%3};" \
        : "+f"((d)[0]), "+f"((d)[1]), "+f"((d)[2]), "+f"((d)[3]) \
        : "r"((a)[0]), "r"((a)[1]), "r"((a)[2]), "r"((a)[3]), "r"(b0), "r"(b1))

#define PACK_BF16X2(r, lo, hi) \
    asm("cvt.rn.bf16x2.f32 %0, %1, %2;" : "=r"(r) : "f"(hi), "f"(lo))

// ---- GEMM smem geometry: CTA 128x128, 8 warps (4x2), warp 32x64 ----
// BKC=32, THREE pipeline stages, ONE barrier per window.
#define BKC     32
#define RS      40
#define TILE_EL (128*RS)                 // 5120
#define XH_OFF  0
#define XL_OFF  TILE_EL
#define WH_OFF  (2*TILE_EL)
#define WL_OFF  (3*TILE_EL)
#define STAGE_EL (4*TILE_EL)             // 20480
#define NSTAGE  3
#define SMEM_MMA (NSTAGE*STAGE_EL*2)     // 122880 B -> 1 CTA/SM

// ---- flash smem geometry (unchanged control) ----
#define FRS    72
#define FTS    (64*FRS)
#define FSTAGE (4*FTS)
#define SMEM_FLASH (2*FSTAGE*2)          // 73728 B

#define NX_ELEMS  ((size_t)MT*DM)
#define NWT_ELEMS ((size_t)DM*DM)
#define PACK_BLKS  ((NB*NW*NW)/256)
#define CONVX_BLKS ((3*MT*DM)/1024)
#define CONVW_BLKS ((4*DM*DM)/1024)
#define PREP_BLKS  (PACK_BLKS + CONVX_BLKS + CONVW_BLKS)

// ============================================================
// prep: mask pack + all fp32->split bf16 conversions, one launch
// ============================================================
__device__ __forceinline__ void conv4_store(const float* __restrict__ src, size_t off,
                                            __nv_bfloat16* __restrict__ hi,
                                            __nv_bfloat16* __restrict__ lo, size_t i) {
    float4 v = *(const float4*)(src + off);
    __nv_bfloat16 h0 = __float2bfloat16(v.x), h1 = __float2bfloat16(v.y);
    __nv_bfloat16 h2 = __float2bfloat16(v.z), h3 = __float2bfloat16(v.w);
    __nv_bfloat16 l0 = __float2bfloat16(v.x - __bfloat162float(h0));
    __nv_bfloat16 l1 = __float2bfloat16(v.y - __bfloat162float(h1));
    __nv_bfloat16 l2 = __float2bfloat16(v.z - __bfloat162float(h2));
    __nv_bfloat16 l3 = __float2bfloat16(v.w - __bfloat162float(h3));
    ((__nv_bfloat162*)(hi + i))[0] = __nv_bfloat162(h0, h1);
    ((__nv_bfloat162*)(hi + i))[1] = __nv_bfloat162(h2, h3);
    ((__nv_bfloat162*)(lo + i))[0] = __nv_bfloat162(l0, l1);
    ((__nv_bfloat162*)(lo + i))[1] = __nv_bfloat162(l2, l3);
}

__global__ void __launch_bounds__(256) prep_kernel(
    const int* __restrict__ mask,
    const float* __restrict__ Q, const float* __restrict__ K, const float* __restrict__ V,
    const float* __restrict__ Wq, const float* __restrict__ Wk,
    const float* __restrict__ Wv, const float* __restrict__ Wo)
{
    int bid = blockIdx.x, tid = threadIdx.x;
    if (bid < PACK_BLKS) {
        int gt = bid * 256 + tid;
        int word = gt >> 5, lane = gt & 31;
        int v = mask[word * 32 + lane];
        unsigned b = __ballot_sync(0xffffffffu, v != 0);
        if (lane == 0) g_mb[word] = b;
        return;
    }
    bid -= PACK_BLKS;
    if (bid < CONVX_BLKS) {
        size_t i = ((size_t)bid * 256 + tid) * 4;
        const float* src; size_t off;
        if (i < NX_ELEMS)            { src = Q; off = i; }
        else if (i < 2 * NX_ELEMS)   { src = K; off = i - NX_ELEMS; }
        else                         { src = V; off = i - 2 * NX_ELEMS; }
        conv4_store(src, off, g_xh, g_xl, i);
        return;
    }
    bid -= CONVX_BLKS;
    {
        size_t i = ((size_t)bid * 256 + tid) * 4;
        const float* src; size_t off;
        if (i < NWT_ELEMS)            { src = Wq; off = i; }
        else if (i < 2 * NWT_ELEMS)   { src = Wk; off = i - NWT_ELEMS; }
        else if (i < 3 * NWT_ELEMS)   { src = Wv; off = i - 2 * NWT_ELEMS; }
        else                          { src = Wo; off = i - 3 * NWT_ELEMS; }
        conv4_store(src, off, g_wh, g_wl, i);
    }
}

// ============================================================
// GEMM: C[128x128] = X[m0:+128,:] * W[n0:+128,:]^T, split-bf16 3-term
// 256 threads, 8 warps (4x2), warp tile 32x64, 3-stage pipeline
// ============================================================
__device__ __forceinline__ void issue_stage(
    const __nv_bfloat16* __restrict__ xh, const __nv_bfloat16* __restrict__ xl,
    const __nv_bfloat16* __restrict__ wh, const __nv_bfloat16* __restrict__ wl,
    int m0, int n0, int kt, uint32_t stage_sb, int tid)
{
    #pragma unroll
    for (int t = 0; t < 8; t++) {
        int tile = t >> 1;                   // 0=Xh 1=Xl 2=Wh 3=Wl
        int rem = tid + (t & 1) * 256;       // 0..511
        int row = rem >> 2, cq = rem & 3;
        const __nv_bfloat16* base = (tile == 0) ? xh : (tile == 1) ? xl
                                   : (tile == 2) ? wh : wl;
        int rb = (tile < 2) ? m0 : n0;
        size_t g = (size_t)(rb + row) * DM + kt * BKC + cq * 8;
        uint32_t sa = stage_sb + (uint32_t)(tile * TILE_EL + row * RS + cq * 8) * 2;
        CP_ASYNC16(sa, base + g);
    }
}

__device__ __forceinline__ void mma_mainloop(
    const __nv_bfloat16* __restrict__ xh, const __nv_bfloat16* __restrict__ xl,
    const __nv_bfloat16* __restrict__ wh, const __nv_bfloat16* __restrict__ wl,
    int m0, int n0, __nv_bfloat16* sbuf, float acc[2][8][4])
{
    int tid = threadIdx.x;
    int wid = tid >> 5, lane = tid & 31;
    int wm = wid >> 1, wn = wid & 1;          // 4x2 warps, warp tile 32x64
    int lr = lane & 15, lc = lane >> 4;

    uint32_t sb = smem_u32(sbuf);
    uint32_t stage_sb[NSTAGE];
    #pragma unroll
    for (int i = 0; i < NSTAGE; i++) stage_sb[i] = sb + (uint32_t)(i * STAGE_EL) * 2;

    const int NKT = DM / BKC;                // 32
    // prologue: issue kt=0, kt=1
    issue_stage(xh, xl, wh, wl, m0, n0, 0, stage_sb[0], tid);
    CP_COMMIT();
    issue_stage(xh, xl, wh, wl, m0, n0, 1, stage_sb[1], tid);
    CP_COMMIT();

    for (int kt = 0; kt < NKT; kt++) {
        int s = kt % NSTAGE;
        // ensure group kt is complete (2-deep wait for kt < NKT-1)
        if (kt < NKT - 1) { CP_WAIT1(); } else { CP_WAIT0(); }
        __syncthreads();    // single barrier: data of kt visible; window kt-1 readers done
        // issue kt+2 into stage (kt+2)%3 — its last readers were window kt-1 (done)
        if (kt + 2 < NKT) {
            issue_stage(xh, xl, wh, wl, m0, n0, kt + 2, stage_sb[(kt + 2) % NSTAGE], tid);
            CP_COMMIT();
        }

        uint32_t ab = stage_sb[s];
        #pragma unroll
        for (int kk = 0; kk < BKC; kk += 16) {
            uint32_t ah[2][4], al[2][4];
            #pragma unroll
            for (int mi = 0; mi < 2; mi++) {
                uint32_t off = (uint32_t)((wm * 32 + mi * 16 + lr) * RS + kk + lc * 8) * 2;
                LDSM4(ah[mi], ab + XH_OFF * 2 + off);
                LDSM4(al[mi], ab + XL_OFF * 2 + off);
            }
            #pragma unroll
            for (int ni = 0; ni < 4; ni++) {
                uint32_t bh[4], bl[4];
                uint32_t off = (uint32_t)((wn * 64 + ni * 16 + lr) * RS + kk + lc * 8) * 2;
                LDSM4(bh, ab + WH_OFF * 2 + off);
                LDSM4(bl, ab + WL_OFF * 2 + off);
                #pragma unroll
                for (int mi = 0; mi < 2; mi++) {
                    #pragma unroll
                    for (int hf = 0; hf < 2; hf++) {
                        MMA16816(acc[mi][ni * 2 + hf], ah[mi], bh[hf], bh[hf + 2]);
                        MMA16816(acc[mi][ni * 2 + hf], ah[mi], bl[hf], bl[hf + 2]);
                        MMA16816(acc[mi][ni * 2 + hf], al[mi], bh[hf], bh[hf + 2]);
                    }
                }
            }
        }
        // NO trailing barrier: 3-stage rotation makes overwrite safe
    }
}

// ============================================================
// Projection GEMM: epilogue writes split-bf16 head-major q/k/v
// ============================================================
__global__ void __launch_bounds__(256, 1) proj_mma_kernel() {
    extern __shared__ __nv_bfloat16 sbuf[];
    int z = blockIdx.z;
    int m0 = blockIdx.y * 128, n0 = blockIdx.x * 128;
    const __nv_bfloat16* xh = g_xh + (size_t)z * MT * DM;
    const __nv_bfloat16* xl = g_xl + (size_t)z * MT * DM;
    const __nv_bfloat16* wh = g_wh + (size_t)z * DM * DM;
    const __nv_bfloat16* wl = g_wl + (size_t)z * DM * DM;
    __nv_bfloat16* dh = (z == 0) ? g_qh : (z == 1) ? g_kh : g_vh;
    __nv_bfloat16* dl = (z == 0) ? g_ql : (z == 1) ? g_kl : g_vl;
    float scale = (z == 0) ? 0.125f : 1.0f;

    float acc[2][8][4];
    #pragma unroll
    for (int i = 0; i < 2; i++)
        #pragma unroll
        for (int j = 0; j < 8; j++)
            acc[i][j][0] = acc[i][j][1] = acc[i][j][2] = acc[i][j][3] = 0.f;

    mma_mainloop(xh, xl, wh, wl, m0, n0, sbuf, acc);

    int tid = threadIdx.x, wid = tid >> 5, lane = tid & 31;
    int wm = wid >> 1, wn = wid & 1;
    int h = (n0 + wn * 64) >> 6;             // warp's 64-wide n-band = one head
    #pragma unroll
    for (int mi = 0; mi < 2; mi++)
        #pragma unroll
        for (int nj = 0; nj < 8; nj++) {
            int d = nj * 8 + (lane & 3) * 2;
            int m = m0 + wm * 32 + mi * 16 + (lane >> 2);
            int bb = m >> 11, t = m & (NW - 1);
            size_t off = ((size_t)(bb * NH + h) * NW + t) * DK + d;
            float v0 = acc[mi][nj][0] * scale, v1 = acc[mi][nj][1] * scale;
            uint32_t hp, lp;
            PACK_BF16X2(hp, v0, v1);
            float f0 = __uint_as_float(hp << 16), f1 = __uint_as_float(hp & 0xffff0000u);
            PACK_BF16X2(lp, v0 - f0, v1 - f1);
            *(uint32_t*)(dh + off) = hp;
            *(uint32_t*)(dl + off) = lp;
            v0 = acc[mi][nj][2] * scale; v1 = acc[mi][nj][3] * scale;
            PACK_BF16X2(hp, v0, v1);
            f0 = __uint_as_float(hp << 16); f1 = __uint_as_float(hp & 0xffff0000u);
            PACK_BF16X2(lp, v0 - f0, v1 - f1);
            *(uint32_t*)(dh + off + 8 * DK) = hp;
            *(uint32_t*)(dl + off + 8 * DK) = lp;
        }
}

// ============================================================
// Output GEMM
// ============================================================
__global__ void __launch_bounds__(256, 1) out_mma_kernel(float* __restrict__ out) {
    extern __shared__ __nv_bfloat16 sbuf[];
    int m0 = blockIdx.y * 128, n0 = blockIdx.x * 128;
    const __nv_bfloat16* wh = g_wh + (size_t)3 * DM * DM;
    const __nv_bfloat16* wl = g_wl + (size_t)3 * DM * DM;

    float acc[2][8][4];
    #pragma unroll
    for (int i = 0; i < 2; i++)
        #pragma unroll
        for (int j = 0; j < 8; j++)
            acc[i][j][0] = acc[i][j][1] = acc[i][j][2] = acc[i][j][3] = 0.f;

    mma_mainloop(g_xh, g_xl, wh, wl, m0, n0, sbuf, acc);

    int tid = threadIdx.x, wid = tid >> 5, lane = tid & 31;
    int wm = wid >> 1, wn = wid & 1;
    #pragma unroll
    for (int mi = 0; mi < 2; mi++)
        #pragma unroll
        for (int nj = 0; nj < 8; nj++) {
            int n = n0 + wn * 64 + nj * 8 + (lane & 3) * 2;
            int m = m0 + wm * 32 + mi * 16 + (lane >> 2);
            *(float2*)(out + (size_t)m * DM + n) = make_float2(acc[mi][nj][0], acc[mi][nj][1]);
            *(float2*)(out + (size_t)(m + 8) * DM + n) = make_float2(acc[mi][nj][2], acc[mi][nj][3]);
        }
}

// ============================================================
// Flash attention (unchanged control): 256 threads, 8 warps, 16 q/warp
// ============================================================
__device__ __forceinline__ void flash_issue(
    const __nv_bfloat16* __restrict__ kh, const __nv_bfloat16* __restrict__ kl,
    const __nv_bfloat16* __restrict__ vh, const __nv_bfloat16* __restrict__ vl,
    int kt, uint32_t stage_sb, int tid)
{
    const __nv_bfloat16* gb[4] = { kh, kl, vh, vl };
    #pragma unroll
    for (int t = 0; t < 8; t++) {
        int tile = t >> 1;
        int rem = tid + (t & 1) * 256;       // 0..511
        int row = rem >> 3, cq = rem & 7;
        const __nv_bfloat16* g = gb[tile] + (size_t)(kt * 64 + row) * DK + cq * 8;
        uint32_t sa = stage_sb + (uint32_t)(tile * FTS + row * FRS + cq * 8) * 2;
        CP_ASYNC16(sa, g);
    }
}

__global__ void __launch_bounds__(256, 2) flash_mma_kernel() {
    extern __shared__ __nv_bfloat16 fsm[];
    int b = blockIdx.z, h = blockIdx.y, q0 = blockIdx.x * 128;
    int tid = threadIdx.x, wid = tid >> 5, lane = tid & 31;
    int lr = lane & 15, lc = lane >> 4;
    int gr = lane >> 2, c = lane & 3;

    size_t hb = (size_t)(b * NH + h) * NW * DK;
    const __nv_bfloat16* kh = g_kh + hb;
    const __nv_bfloat16* kl = g_kl + hb;
    const __nv_bfloat16* vh = g_vh + hb;
    const __nv_bfloat16* vl = g_vl + hb;
    const __nv_bfloat16* qh = g_qh + hb + (size_t)q0 * DK;
    const __nv_bfloat16* ql = g_ql + hb + (size_t)q0 * DK;

    uint32_t qhf[4][4];
    #pragma unroll
    for (int kc = 0; kc < 4; kc++) {
        int r0 = wid * 16 + gr, col = kc * 16 + 2 * c;
        qhf[kc][0] = *(const uint32_t*)(qh + (size_t)r0 * DK + col);
        qhf[kc][1] = *(const uint32_t*)(qh + (size_t)(r0 + 8) * DK + col);
        qhf[kc][2] = *(const uint32_t*)(qh + (size_t)r0 * DK + col + 8);
        qhf[kc][3] = *(const uint32_t*)(qh + (size_t)(r0 + 8) * DK + col + 8);
    }

    float oacc[8][4];
    #pragma unroll
    for (int j = 0; j < 8; j++)
        oacc[j][0] = oacc[j][1] = oacc[j][2] = oacc[j][3] = 0.f;
    float m0 = -INFINITY, m1 = -INFINITY, l0 = 0.f, l1 = 0.f;

    uint32_t sb = smem_u32(fsm);
    flash_issue(kh, kl, vh, vl, 0, sb, tid);
    CP_COMMIT();

    for (int kt = 0; kt < NW / 64; kt++) {
        int s = kt & 1;
        uint32_t ss = sb + (uint32_t)(s * FSTAGE) * 2;
        if (kt < NW / 64 - 1) {
            flash_issue(kh, kl, vh, vl, kt + 1, sb + (uint32_t)((s ^ 1) * FSTAGE) * 2, tid);
            CP_COMMIT();
            CP_WAIT1();
        } else {
            CP_WAIT0();
        }
        __syncthreads();

        const unsigned* mb0 = g_mb + (size_t)(b * NW + q0 + wid * 16 + gr) * MWPR + kt * 2;
        unsigned mw00 = mb0[0], mw01 = mb0[1];
        unsigned mw10 = mb0[8 * MWPR], mw11 = mb0[8 * MWPR + 1];

        float sacc[8][4];
        #pragma unroll
        for (int j = 0; j < 8; j++)
            sacc[j][0] = sacc[j][1] = sacc[j][2] = sacc[j][3] = 0.f;

        #pragma unroll
        for (int kc = 0; kc < 4; kc++) {
            uint32_t qlf[4];
            {
                int r0 = wid * 16 + gr, col = kc * 16 + 2 * c;
                qlf[0] = *(const uint32_t*)(ql + (size_t)r0 * DK + col);
                qlf[1] = *(const uint32_t*)(ql + (size_t)(r0 + 8) * DK + col);
                qlf[2] = *(const uint32_t*)(ql + (size_t)r0 * DK + col + 8);
                qlf[3] = *(const uint32_t*)(ql + (size_t)(r0 + 8) * DK + col + 8);
            }
            #pragma unroll
            for (int g = 0; g < 4; g++) {
                uint32_t khf[4], klf[4];
                uint32_t off = (uint32_t)((g * 16 + lr) * FRS + kc * 16 + lc * 8) * 2;
                LDSM4(khf, ss + off);
                LDSM4(klf, ss + (uint32_t)FTS * 2 + off);
                #pragma unroll
                for (int hf = 0; hf < 2; hf++) {
                    MMA16816(sacc[2 * g + hf], qhf[kc], khf[hf], khf[hf + 2]);
                    MMA16816(sacc[2 * g + hf], qhf[kc], klf[hf], klf[hf + 2]);
                    MMA16816(sacc[2 * g + hf], qlf,     khf[hf], khf[hf + 2]);
                }
            }
        }

        #pragma unroll
        for (int j = 0; j < 8; j++) {
            unsigned wr0 = (j < 4) ? mw00 : mw01;
            unsigned wr1 = (j < 4) ? mw10 : mw11;
            int bit = (8 * j + 2 * c) & 31;
            if (!((wr0 >> bit) & 1u))       sacc[j][0] = -1e9f;
            if (!((wr0 >> (bit + 1)) & 1u)) sacc[j][1] = -1e9f;
            if (!((wr1 >> bit) & 1u))       sacc[j][2] = -1e9f;
            if (!((wr1 >> (bit + 1)) & 1u)) sacc[j][3] = -1e9f;
        }

        float mx0 = -INFINITY, mx1 = -INFINITY;
        #pragma unroll
        for (int j = 0; j < 8; j++) {
            mx0 = fmaxf(mx0, fmaxf(sacc[j][0], sacc[j][1]));
            mx1 = fmaxf(mx1, fmaxf(sacc[j][2], sacc[j][3]));
        }
        mx0 = fmaxf(mx0, __shfl_xor_sync(0xffffffffu, mx0, 1));
        mx0 = fmaxf(mx0, __shfl_xor_sync(0xffffffffu, mx0, 2));
        mx1 = fmaxf(mx1, __shfl_xor_sync(0xffffffffu, mx1, 1));
        mx1 = fmaxf(mx1, __shfl_xor_sync(0xffffffffu, mx1, 2));

        float nm0 = fmaxf(m0, mx0), nm1 = fmaxf(m1, mx1);
        float sc0 = __expf(m0 - nm0), sc1 = __expf(m1 - nm1);
        float rs0 = 0.f, rs1 = 0.f;
        #pragma unroll
        for (int j = 0; j < 8; j++) {
            sacc[j][0] = __expf(sacc[j][0] - nm0);
            sacc[j][1] = __expf(sacc[j][1] - nm0);
            sacc[j][2] = __expf(sacc[j][2] - nm1);
            sacc[j][3] = __expf(sacc[j][3] - nm1);
            rs0 += sacc[j][0] + sacc[j][1];
            rs1 += sacc[j][2] + sacc[j][3];
        }
        rs0 += __shfl_xor_sync(0xffffffffu, rs0, 1);
        rs0 += __shfl_xor_sync(0xffffffffu, rs0, 2);
        rs1 += __shfl_xor_sync(0xffffffffu, rs1, 1);
        rs1 += __shfl_xor_sync(0xffffffffu, rs1, 2);
        m0 = nm0; m1 = nm1;
        l0 = l0 * sc0 + rs0;
        l1 = l1 * sc1 + rs1;
        #pragma unroll
        for (int j = 0; j < 8; j++) {
            oacc[j][0] *= sc0; oacc[j][1] *= sc0;
            oacc[j][2] *= sc1; oacc[j][3] *= sc1;
        }

        uint32_t phf[4][4], plf[4][4];
        #pragma unroll
        for (int kc = 0; kc < 4; kc++) {
            #pragma unroll
            for (int q = 0; q < 4; q++) {
                int jt = 2 * kc + (q >> 1);
                float p0 = sacc[jt][(q & 1) ? 2 : 0];
                float p1 = sacc[jt][(q & 1) ? 3 : 1];
                uint32_t hp, lp;
                PACK_BF16X2(hp, p0, p1);
                float f0 = __uint_as_float(hp << 16);
                float f1 = __uint_as_float(hp & 0xffff0000u);
                PACK_BF16X2(lp, p0 - f0, p1 - f1);
                phf[kc][q] = hp; plf[kc][q] = lp;
            }
        }

        #pragma unroll
        for (int kc = 0; kc < 4; kc++) {
            #pragma unroll
            for (int dg = 0; dg < 4; dg++) {
                uint32_t vhf[4], vlf[4];
                uint32_t off = (uint32_t)((kc * 16 + lr) * FRS + dg * 16 + lc * 8) * 2;
                LDSM4T(vhf, ss + (uint32_t)(2 * FTS) * 2 + off);
                LDSM4T(vlf, ss + (uint32_t)(3 * FTS) * 2 + off);
                MMA16816(oacc[2 * dg],     phf[kc], vhf[0], vhf[1]);
                MMA16816(oacc[2 * dg],     plf[kc], vhf[0], vhf[1]);
                MMA16816(oacc[2 * dg],     phf[kc], vlf[0], vlf[1]);
                MMA16816(oacc[2 * dg + 1], phf[kc], vhf[2], vhf[3]);
                MMA16816(oacc[2 * dg + 1], plf[kc], vhf[2], vhf[3]);
                MMA16816(oacc[2 * dg + 1], phf[kc], vlf[2], vlf[3]);
            }
        }
        __syncthreads();
    }

    float inv0 = 1.f / l0, inv1 = 1.f / l1;
    int row0 = q0 + wid * 16 + gr;
    size_t base0 = ((size_t)b * NW + row0) * DM + h * DK;
    #pragma unroll
    for (int j = 0; j < 8; j++) {
        int d = 8 * j + 2 * c;
        float v0 = oacc[j][0] * inv0, v1 = oacc[j][1] * inv0;
        uint32_t hp, lp;
        PACK_BF16X2(hp, v0, v1);
        float f0 = __uint_as_float(hp << 16), f1 = __uint_as_float(hp & 0xffff0000u);
        PACK_BF16X2(lp, v0 - f0, v1 - f1);
        *(uint32_t*)((__nv_bfloat16*)g_xh + base0 + d) = hp;
        *(uint32_t*)((__nv_bfloat16*)g_xl + base0 + d) = lp;
        v0 = oacc[j][2] * inv1; v1 = oacc[j][3] * inv1;
        PACK_BF16X2(hp, v0, v1);
        f0 = __uint_as_float(hp << 16); f1 = __uint_as_float(hp & 0xffff0000u);
        PACK_BF16X2(lp, v0 - f0, v1 - f1);
        *(uint32_t*)((__nv_bfloat16*)g_xh + base0 + 8 * DM + d) = hp;
        *(uint32_t*)((__nv_bfloat16*)g_xl + base0 + 8 * DM + d) = lp;
    }
}

// ============================================================
extern "C" void kernel_launch(void* const* d_in, const int* in_sizes, int n_in,
                              void* d_out, int out_size) {
    const float* Q  = (const float*)d_in[0];
    const float* K  = (const float*)d_in[1];
    const float* V  = (const float*)d_in[2];
    const int* mask = (const int*)d_in[3];
    const float* Wq = (const float*)d_in[4];
    const float* Wk = (const float*)d_in[5];
    const float* Wv = (const float*)d_in[6];
    const float* Wo = (const float*)d_in[7];
    float* out = (float*)d_out;

    static int attr_done = 0;
    if (!attr_done) {
        cudaFuncSetAttribute(proj_mma_kernel, cudaFuncAttributeMaxDynamicSharedMemorySize, SMEM_MMA);
        cudaFuncSetAttribute(out_mma_kernel, cudaFuncAttributeMaxDynamicSharedMemorySize, SMEM_MMA);
        cudaFuncSetAttribute(flash_mma_kernel, cudaFuncAttributeMaxDynamicSharedMemorySize, SMEM_FLASH);
        attr_done = 1;
    }

    prep_kernel<<<PREP_BLKS, 256>>>(mask, Q, K, V, Wq, Wk, Wv, Wo);
    proj_mma_kernel<<<dim3(DM / 128, MT / 128, 3), 256, SMEM_MMA>>>();
    flash_mma_kernel<<<dim3(NW / 128, NH, NB), 256, SMEM_FLASH>>>();
    out_mma_kernel<<<dim3(DM / 128, MT / 128), 256, SMEM_MMA>>>(out);
}

// round 11
// speedup vs baseline: 1.0909x; 1.0909x over previous
#include <cuda_runtime.h>
#include <cuda_bf16.h>
#include <cstdint>
#include <math.h>

#define NB 4
#define NW 2048
#define DM 1024
#define NH 16
#define DK 64
#define MT (NB*NW)
#define MWPR (NW/32)

// ---------------- device scratch ----------------
__device__ unsigned g_mb[NB*NW*MWPR];
__device__ __nv_bfloat16 g_xh[3u*MT*DM];   // hi of Q,K,V inputs (slot 0 reused for attn out)
__device__ __nv_bfloat16 g_xl[3u*MT*DM];
__device__ __nv_bfloat16 g_wh[4u*DM*DM];
__device__ __nv_bfloat16 g_wl[4u*DM*DM];
__device__ __nv_bfloat16 g_qh[NB*NH*NW*DK];
__device__ __nv_bfloat16 g_ql[NB*NH*NW*DK];
__device__ __nv_bfloat16 g_kh[NB*NH*NW*DK];
__device__ __nv_bfloat16 g_kl[NB*NH*NW*DK];
__device__ __nv_bfloat16 g_vh[NB*NH*NW*DK];
__device__ __nv_bfloat16 g_vl[NB*NH*NW*DK];

// ---------------- PTX helpers ----------------
__device__ __forceinline__ uint32_t smem_u32(const void* p) {
    uint32_t a;
    asm("{ .reg .u64 t; cvta.to.shared.u64 t, %1; cvt.u32.u64 %0, t; }" : "=r"(a) : "l"(p));
    return a;
}
#define CP_ASYNC16(sa, g) \
    asm volatile("cp.async.cg.shared.global [%0], [%1], 16;" :: "r"(sa), "l"(g))
#define CP_COMMIT() asm volatile("cp.async.commit_group;" ::: "memory")
#define CP_WAIT1()  asm volatile("cp.async.wait_group 1;" ::: "memory")
#define CP_WAIT0()  asm volatile("cp.async.wait_group 0;" ::: "memory")

#define LDSM4(r, addr) \
    asm volatile("ldmatrix.sync.aligned.m8n8.x4.shared.b16 {%0,%1,%2,%3}, [%4];" \
        : "=r"((r)[0]), "=r"((r)[1]), "=r"((r)[2]), "=r"((r)[3]) : "r"(addr))
#define LDSM4T(r, addr) \
    asm volatile("ldmatrix.sync.aligned.m8n8.x4.trans.shared.b16 {%0,%1,%2,%3}, [%4];" \
        : "=r"((r)[0]), "=r"((r)[1]), "=r"((r)[2]), "=r"((r)[3]) : "r"(addr))

#define MMA16816(d, a, b0, b1) \
    asm volatile("mma.sync.aligned.m16n8k16.row.col.f32.bf16.bf16.f32 " \
        "{%0,%1,%2,%3}, {%4,%5,%6,%7}, {%8,%9}, {%0,%1,%2,%3};" \
        : "+f"((d)[0]), "+f"((d)[1]), "+f"((d)[2]), "+f"((d)[3]) \
        : "r"((a)[0]), "r"((a)[1]), "r"((a)[2]), "r"((a)[3]), "r"(b0), "r"(b1))

#define PACK_BF16X2(r, lo, hi) \
    asm("cvt.rn.bf16x2.f32 %0, %1, %2;" : "=r"(r) : "f"(hi), "f"(lo))

// ---- GEMM smem geometry (R8 proven): CTA 128x128, 8 warps (4x2), warp 32x64, 2 stages ----
#define BKC    32
#define RS     40
#define XH_OFF 0
#define XL_OFF 5120
#define WH_OFF 10240
#define WL_OFF 15360
#define STAGE_EL 20480
#define SMEM_MMA (2*STAGE_EL*2)         // 81920 B -> 2 CTAs/SM

// ---- flash smem geometry ----
#define FRS    72
#define FTS    (64*FRS)
#define FSTAGE (4*FTS)
#define SMEM_FLASH (2*FSTAGE*2)          // 73728 B

#define NX_ELEMS  ((size_t)MT*DM)
#define NWT_ELEMS ((size_t)DM*DM)
#define PACK_BLKS  ((NB*NW*NW)/256)
#define CONVX_BLKS ((3*MT*DM)/1024)
#define CONVW_BLKS ((4*DM*DM)/1024)
#define PREP_BLKS  (PACK_BLKS + CONVX_BLKS + CONVW_BLKS)

// ============================================================
// prep: mask pack + all fp32->split bf16 conversions, one launch
// ============================================================
__device__ __forceinline__ void conv4_store(const float* __restrict__ src, size_t off,
                                            __nv_bfloat16* __restrict__ hi,
                                            __nv_bfloat16* __restrict__ lo, size_t i) {
    float4 v = *(const float4*)(src + off);
    __nv_bfloat16 h0 = __float2bfloat16(v.x), h1 = __float2bfloat16(v.y);
    __nv_bfloat16 h2 = __float2bfloat16(v.z), h3 = __float2bfloat16(v.w);
    __nv_bfloat16 l0 = __float2bfloat16(v.x - __bfloat162float(h0));
    __nv_bfloat16 l1 = __float2bfloat16(v.y - __bfloat162float(h1));
    __nv_bfloat16 l2 = __float2bfloat16(v.z - __bfloat162float(h2));
    __nv_bfloat16 l3 = __float2bfloat16(v.w - __bfloat162float(h3));
    ((__nv_bfloat162*)(hi + i))[0] = __nv_bfloat162(h0, h1);
    ((__nv_bfloat162*)(hi + i))[1] = __nv_bfloat162(h2, h3);
    ((__nv_bfloat162*)(lo + i))[0] = __nv_bfloat162(l0, l1);
    ((__nv_bfloat162*)(lo + i))[1] = __nv_bfloat162(l2, l3);
}

__global__ void __launch_bounds__(256) prep_kernel(
    const int* __restrict__ mask,
    const float* __restrict__ Q, const float* __restrict__ K, const float* __restrict__ V,
    const float* __restrict__ Wq, const float* __restrict__ Wk,
    const float* __restrict__ Wv, const float* __restrict__ Wo)
{
    int bid = blockIdx.x, tid = threadIdx.x;
    if (bid < PACK_BLKS) {
        int gt = bid * 256 + tid;
        int word = gt >> 5, lane = gt & 31;
        int v = mask[word * 32 + lane];
        unsigned b = __ballot_sync(0xffffffffu, v != 0);
        if (lane == 0) g_mb[word] = b;
        return;
    }
    bid -= PACK_BLKS;
    if (bid < CONVX_BLKS) {
        size_t i = ((size_t)bid * 256 + tid) * 4;
        const float* src; size_t off;
        if (i < NX_ELEMS)            { src = Q; off = i; }
        else if (i < 2 * NX_ELEMS)   { src = K; off = i - NX_ELEMS; }
        else                         { src = V; off = i - 2 * NX_ELEMS; }
        conv4_store(src, off, g_xh, g_xl, i);
        return;
    }
    bid -= CONVX_BLKS;
    {
        size_t i = ((size_t)bid * 256 + tid) * 4;
        const float* src; size_t off;
        if (i < NWT_ELEMS)            { src = Wq; off = i; }
        else if (i < 2 * NWT_ELEMS)   { src = Wk; off = i - NWT_ELEMS; }
        else if (i < 3 * NWT_ELEMS)   { src = Wv; off = i - 2 * NWT_ELEMS; }
        else                          { src = Wo; off = i - 3 * NWT_ELEMS; }
        conv4_store(src, off, g_wh, g_wl, i);
    }
}

// ============================================================
// GEMM: C[128x128] = X[m0:+128,:] * W[n0:+128,:]^T, split-bf16 3-term
// 256 threads, 8 warps (4x2), warp tile 32x64 — TERM-MAJOR MMA issue
// ============================================================
__device__ __forceinline__ void issue_stage(
    const __nv_bfloat16* __restrict__ xh, const __nv_bfloat16* __restrict__ xl,
    const __nv_bfloat16* __restrict__ wh, const __nv_bfloat16* __restrict__ wl,
    int m0, int n0, int kt, uint32_t stage_sb, int tid)
{
    #pragma unroll
    for (int t = 0; t < 8; t++) {
        int tile = t >> 1;                   // 0=Xh 1=Xl 2=Wh 3=Wl
        int rem = tid + (t & 1) * 256;       // 0..511
        int row = rem >> 2, cq = rem & 3;
        const __nv_bfloat16* base = (tile == 0) ? xh : (tile == 1) ? xl
                                   : (tile == 2) ? wh : wl;
        int rb = (tile < 2) ? m0 : n0;
        size_t g = (size_t)(rb + row) * DM + kt * BKC + cq * 8;
        uint32_t sa = stage_sb + (uint32_t)(tile * 5120 + row * RS + cq * 8) * 2;
        CP_ASYNC16(sa, base + g);
    }
}

__device__ __forceinline__ void mma_mainloop(
    const __nv_bfloat16* __restrict__ xh, const __nv_bfloat16* __restrict__ xl,
    const __nv_bfloat16* __restrict__ wh, const __nv_bfloat16* __restrict__ wl,
    int m0, int n0, __nv_bfloat16* sbuf, float acc[2][8][4])
{
    int tid = threadIdx.x;
    int wid = tid >> 5, lane = tid & 31;
    int wm = wid >> 1, wn = wid & 1;          // 4x2 warps, warp tile 32x64
    int lr = lane & 15, lc = lane >> 4;

    uint32_t sb = smem_u32(sbuf);
    uint32_t stage_sb[2] = { sb, sb + (uint32_t)STAGE_EL * 2 };

    issue_stage(xh, xl, wh, wl, m0, n0, 0, stage_sb[0], tid);
    CP_COMMIT();

    for (int kt = 0; kt < DM / BKC; kt++) {
        int s = kt & 1;
        if (kt < DM / BKC - 1) {
            issue_stage(xh, xl, wh, wl, m0, n0, kt + 1, stage_sb[s ^ 1], tid);
            CP_COMMIT();
            CP_WAIT1();
        } else {
            CP_WAIT0();
        }
        __syncthreads();

        uint32_t ab = stage_sb[s];
        #pragma unroll
        for (int kk = 0; kk < BKC; kk += 16) {
            uint32_t ah[2][4], al[2][4];
            #pragma unroll
            for (int mi = 0; mi < 2; mi++) {
                uint32_t off = (uint32_t)((wm * 32 + mi * 16 + lr) * RS + kk + lc * 8) * 2;
                LDSM4(ah[mi], ab + XH_OFF * 2 + off);
                LDSM4(al[mi], ab + XL_OFF * 2 + off);
            }
            #pragma unroll
            for (int ni = 0; ni < 4; ni++) {
                uint32_t bh[4], bl[4];
                uint32_t off = (uint32_t)((wn * 64 + ni * 16 + lr) * RS + kk + lc * 8) * 2;
                LDSM4(bh, ab + WH_OFF * 2 + off);
                LDSM4(bl, ab + WL_OFF * 2 + off);
                // TERM-MAJOR: 4 independent accs per term; same-acc distance = 4
                #pragma unroll
                for (int mi = 0; mi < 2; mi++)
                    #pragma unroll
                    for (int hf = 0; hf < 2; hf++)
                        MMA16816(acc[mi][ni * 2 + hf], ah[mi], bh[hf], bh[hf + 2]);
                #pragma unroll
                for (int mi = 0; mi < 2; mi++)
                    #pragma unroll
                    for (int hf = 0; hf < 2; hf++)
                        MMA16816(acc[mi][ni * 2 + hf], ah[mi], bl[hf], bl[hf + 2]);
                #pragma unroll
                for (int mi = 0; mi < 2; mi++)
                    #pragma unroll
                    for (int hf = 0; hf < 2; hf++)
                        MMA16816(acc[mi][ni * 2 + hf], al[mi], bh[hf], bh[hf + 2]);
            }
        }
        __syncthreads();
    }
}

// ============================================================
// Projection GEMM: epilogue writes split-bf16 head-major q/k/v
// ============================================================
__global__ void __launch_bounds__(256, 2) proj_mma_kernel() {
    extern __shared__ __nv_bfloat16 sbuf[];
    int z = blockIdx.z;
    int m0 = blockIdx.y * 128, n0 = blockIdx.x * 128;
    const __nv_bfloat16* xh = g_xh + (size_t)z * MT * DM;
    const __nv_bfloat16* xl = g_xl + (size_t)z * MT * DM;
    const __nv_bfloat16* wh = g_wh + (size_t)z * DM * DM;
    const __nv_bfloat16* wl = g_wl + (size_t)z * DM * DM;
    __nv_bfloat16* dh = (z == 0) ? g_qh : (z == 1) ? g_kh : g_vh;
    __nv_bfloat16* dl = (z == 0) ? g_ql : (z == 1) ? g_kl : g_vl;
    float scale = (z == 0) ? 0.125f : 1.0f;

    float acc[2][8][4];
    #pragma unroll
    for (int i = 0; i < 2; i++)
        #pragma unroll
        for (int j = 0; j < 8; j++)
            acc[i][j][0] = acc[i][j][1] = acc[i][j][2] = acc[i][j][3] = 0.f;

    mma_mainloop(xh, xl, wh, wl, m0, n0, sbuf, acc);

    int tid = threadIdx.x, wid = tid >> 5, lane = tid & 31;
    int wm = wid >> 1, wn = wid & 1;
    int h = (n0 + wn * 64) >> 6;             // warp's 64-wide n-band = one head
    #pragma unroll
    for (int mi = 0; mi < 2; mi++)
        #pragma unroll
        for (int nj = 0; nj < 8; nj++) {
            int d = nj * 8 + (lane & 3) * 2;
            int m = m0 + wm * 32 + mi * 16 + (lane >> 2);
            int bb = m >> 11, t = m & (NW - 1);
            size_t off = ((size_t)(bb * NH + h) * NW + t) * DK + d;
            float v0 = acc[mi][nj][0] * scale, v1 = acc[mi][nj][1] * scale;
            uint32_t hp, lp;
            PACK_BF16X2(hp, v0, v1);
            float f0 = __uint_as_float(hp << 16), f1 = __uint_as_float(hp & 0xffff0000u);
            PACK_BF16X2(lp, v0 - f0, v1 - f1);
            *(uint32_t*)(dh + off) = hp;
            *(uint32_t*)(dl + off) = lp;
            v0 = acc[mi][nj][2] * scale; v1 = acc[mi][nj][3] * scale;
            PACK_BF16X2(hp, v0, v1);
            f0 = __uint_as_float(hp << 16); f1 = __uint_as_float(hp & 0xffff0000u);
            PACK_BF16X2(lp, v0 - f0, v1 - f1);
            *(uint32_t*)(dh + off + 8 * DK) = hp;
            *(uint32_t*)(dl + off + 8 * DK) = lp;
        }
}

// ============================================================
// Output GEMM
// ============================================================
__global__ void __launch_bounds__(256, 2) out_mma_kernel(float* __restrict__ out) {
    extern __shared__ __nv_bfloat16 sbuf[];
    int m0 = blockIdx.y * 128, n0 = blockIdx.x * 128;
    const __nv_bfloat16* wh = g_wh + (size_t)3 * DM * DM;
    const __nv_bfloat16* wl = g_wl + (size_t)3 * DM * DM;

    float acc[2][8][4];
    #pragma unroll
    for (int i = 0; i < 2; i++)
        #pragma unroll
        for (int j = 0; j < 8; j++)
            acc[i][j][0] = acc[i][j][1] = acc[i][j][2] = acc[i][j][3] = 0.f;

    mma_mainloop(g_xh, g_xl, wh, wl, m0, n0, sbuf, acc);

    int tid = threadIdx.x, wid = tid >> 5, lane = tid & 31;
    int wm = wid >> 1, wn = wid & 1;
    #pragma unroll
    for (int mi = 0; mi < 2; mi++)
        #pragma unroll
        for (int nj = 0; nj < 8; nj++) {
            int n = n0 + wn * 64 + nj * 8 + (lane & 3) * 2;
            int m = m0 + wm * 32 + mi * 16 + (lane >> 2);
            *(float2*)(out + (size_t)m * DM + n) = make_float2(acc[mi][nj][0], acc[mi][nj][1]);
            *(float2*)(out + (size_t)(m + 8) * DM + n) = make_float2(acc[mi][nj][2], acc[mi][nj][3]);
        }
}

// ============================================================
// Flash attention: 256 threads, 8 warps, 16 q/warp, 2 CTAs/SM
// TERM-MAJOR MMA issue in S and PV loops
// ============================================================
__device__ __forceinline__ void flash_issue(
    const __nv_bfloat16* __restrict__ kh, const __nv_bfloat16* __restrict__ kl,
    const __nv_bfloat16* __restrict__ vh, const __nv_bfloat16* __restrict__ vl,
    int kt, uint32_t stage_sb, int tid)
{
    const __nv_bfloat16* gb[4] = { kh, kl, vh, vl };
    #pragma unroll
    for (int t = 0; t < 8; t++) {
        int tile = t >> 1;
        int rem = tid + (t & 1) * 256;       // 0..511
        int row = rem >> 3, cq = rem & 7;
        const __nv_bfloat16* g = gb[tile] + (size_t)(kt * 64 + row) * DK + cq * 8;
        uint32_t sa = stage_sb + (uint32_t)(tile * FTS + row * FRS + cq * 8) * 2;
        CP_ASYNC16(sa, g);
    }
}

__global__ void __launch_bounds__(256, 2) flash_mma_kernel() {
    extern __shared__ __nv_bfloat16 fsm[];
    int b = blockIdx.z, h = blockIdx.y, q0 = blockIdx.x * 128;
    int tid = threadIdx.x, wid = tid >> 5, lane = tid & 31;
    int lr = lane & 15, lc = lane >> 4;
    int gr = lane >> 2, c = lane & 3;

    size_t hb = (size_t)(b * NH + h) * NW * DK;
    const __nv_bfloat16* kh = g_kh + hb;
    const __nv_bfloat16* kl = g_kl + hb;
    const __nv_bfloat16* vh = g_vh + hb;
    const __nv_bfloat16* vl = g_vl + hb;
    const __nv_bfloat16* qh = g_qh + hb + (size_t)q0 * DK;
    const __nv_bfloat16* ql = g_ql + hb + (size_t)q0 * DK;

    uint32_t qhf[4][4];
    #pragma unroll
    for (int kc = 0; kc < 4; kc++) {
        int r0 = wid * 16 + gr, col = kc * 16 + 2 * c;
        qhf[kc][0] = *(const uint32_t*)(qh + (size_t)r0 * DK + col);
        qhf[kc][1] = *(const uint32_t*)(qh + (size_t)(r0 + 8) * DK + col);
        qhf[kc][2] = *(const uint32_t*)(qh + (size_t)r0 * DK + col + 8);
        qhf[kc][3] = *(const uint32_t*)(qh + (size_t)(r0 + 8) * DK + col + 8);
    }

    float oacc[8][4];
    #pragma unroll
    for (int j = 0; j < 8; j++)
        oacc[j][0] = oacc[j][1] = oacc[j][2] = oacc[j][3] = 0.f;
    float m0 = -INFINITY, m1 = -INFINITY, l0 = 0.f, l1 = 0.f;

    uint32_t sb = smem_u32(fsm);
    flash_issue(kh, kl, vh, vl, 0, sb, tid);
    CP_COMMIT();

    for (int kt = 0; kt < NW / 64; kt++) {
        int s = kt & 1;
        uint32_t ss = sb + (uint32_t)(s * FSTAGE) * 2;
        if (kt < NW / 64 - 1) {
            flash_issue(kh, kl, vh, vl, kt + 1, sb + (uint32_t)((s ^ 1) * FSTAGE) * 2, tid);
            CP_COMMIT();
            CP_WAIT1();
        } else {
            CP_WAIT0();
        }
        __syncthreads();

        const unsigned* mb0 = g_mb + (size_t)(b * NW + q0 + wid * 16 + gr) * MWPR + kt * 2;
        unsigned mw00 = mb0[0], mw01 = mb0[1];
        unsigned mw10 = mb0[8 * MWPR], mw11 = mb0[8 * MWPR + 1];

        float sacc[8][4];
        #pragma unroll
        for (int j = 0; j < 8; j++)
            sacc[j][0] = sacc[j][1] = sacc[j][2] = sacc[j][3] = 0.f;

        #pragma unroll
        for (int kc = 0; kc < 4; kc++) {
            uint32_t qlf[4];
            {
                int r0 = wid * 16 + gr, col = kc * 16 + 2 * c;
                qlf[0] = *(const uint32_t*)(ql + (size_t)r0 * DK + col);
                qlf[1] = *(const uint32_t*)(ql + (size_t)(r0 + 8) * DK + col);
                qlf[2] = *(const uint32_t*)(ql + (size_t)r0 * DK + col + 8);
                qlf[3] = *(const uint32_t*)(ql + (size_t)(r0 + 8) * DK + col + 8);
            }
            #pragma unroll
            for (int g = 0; g < 4; g++) {
                uint32_t khf[4], klf[4];
                uint32_t off = (uint32_t)((g * 16 + lr) * FRS + kc * 16 + lc * 8) * 2;
                LDSM4(khf, ss + off);
                LDSM4(klf, ss + (uint32_t)FTS * 2 + off);
                // TERM-MAJOR: same-acc distance = 2
                #pragma unroll
                for (int hf = 0; hf < 2; hf++)
                    MMA16816(sacc[2 * g + hf], qhf[kc], khf[hf], khf[hf + 2]);
                #pragma unroll
                for (int hf = 0; hf < 2; hf++)
                    MMA16816(sacc[2 * g + hf], qhf[kc], klf[hf], klf[hf + 2]);
                #pragma unroll
                for (int hf = 0; hf < 2; hf++)
                    MMA16816(sacc[2 * g + hf], qlf,     khf[hf], khf[hf + 2]);
            }
        }

        #pragma unroll
        for (int j = 0; j < 8; j++) {
            unsigned wr0 = (j < 4) ? mw00 : mw01;
            unsigned wr1 = (j < 4) ? mw10 : mw11;
            int bit = (8 * j + 2 * c) & 31;
            if (!((wr0 >> bit) & 1u))       sacc[j][0] = -1e9f;
            if (!((wr0 >> (bit + 1)) & 1u)) sacc[j][1] = -1e9f;
            if (!((wr1 >> bit) & 1u))       sacc[j][2] = -1e9f;
            if (!((wr1 >> (bit + 1)) & 1u)) sacc[j][3] = -1e9f;
        }

        float mx0 = -INFINITY, mx1 = -INFINITY;
        #pragma unroll
        for (int j = 0; j < 8; j++) {
            mx0 = fmaxf(mx0, fmaxf(sacc[j][0], sacc[j][1]));
            mx1 = fmaxf(mx1, fmaxf(sacc[j][2], sacc[j][3]));
        }
        mx0 = fmaxf(mx0, __shfl_xor_sync(0xffffffffu, mx0, 1));
        mx0 = fmaxf(mx0, __shfl_xor_sync(0xffffffffu, mx0, 2));
        mx1 = fmaxf(mx1, __shfl_xor_sync(0xffffffffu, mx1, 1));
        mx1 = fmaxf(mx1, __shfl_xor_sync(0xffffffffu, mx1, 2));

        float nm0 = fmaxf(m0, mx0), nm1 = fmaxf(m1, mx1);
        float sc0 = __expf(m0 - nm0), sc1 = __expf(m1 - nm1);
        float rs0 = 0.f, rs1 = 0.f;
        #pragma unroll
        for (int j = 0; j < 8; j++) {
            sacc[j][0] = __expf(sacc[j][0] - nm0);
            sacc[j][1] = __expf(sacc[j][1] - nm0);
            sacc[j][2] = __expf(sacc[j][2] - nm1);
            sacc[j][3] = __expf(sacc[j][3] - nm1);
            rs0 += sacc[j][0] + sacc[j][1];
            rs1 += sacc[j][2] + sacc[j][3];
        }
        rs0 += __shfl_xor_sync(0xffffffffu, rs0, 1);
        rs0 += __shfl_xor_sync(0xffffffffu, rs0, 2);
        rs1 += __shfl_xor_sync(0xffffffffu, rs1, 1);
        rs1 += __shfl_xor_sync(0xffffffffu, rs1, 2);
        m0 = nm0; m1 = nm1;
        l0 = l0 * sc0 + rs0;
        l1 = l1 * sc1 + rs1;
        #pragma unroll
        for (int j = 0; j < 8; j++) {
            oacc[j][0] *= sc0; oacc[j][1] *= sc0;
            oacc[j][2] *= sc1; oacc[j][3] *= sc1;
        }

        uint32_t phf[4][4], plf[4][4];
        #pragma unroll
        for (int kc = 0; kc < 4; kc++) {
            #pragma unroll
            for (int q = 0; q < 4; q++) {
                int jt = 2 * kc + (q >> 1);
                float p0 = sacc[jt][(q & 1) ? 2 : 0];
                float p1 = sacc[jt][(q & 1) ? 3 : 1];
                uint32_t hp, lp;
                PACK_BF16X2(hp, p0, p1);
                float f0 = __uint_as_float(hp << 16);
                float f1 = __uint_as_float(hp & 0xffff0000u);
                PACK_BF16X2(lp, p0 - f0, p1 - f1);
                phf[kc][q] = hp; plf[kc][q] = lp;
            }
        }

        #pragma unroll
        for (int kc = 0; kc < 4; kc++) {
            #pragma unroll
            for (int dg = 0; dg < 4; dg++) {
                uint32_t vhf[4], vlf[4];
                uint32_t off = (uint32_t)((kc * 16 + lr) * FRS + dg * 16 + lc * 8) * 2;
                LDSM4T(vhf, ss + (uint32_t)(2 * FTS) * 2 + off);
                LDSM4T(vlf, ss + (uint32_t)(3 * FTS) * 2 + off);
                // TERM-MAJOR: same-acc distance = 2
                MMA16816(oacc[2 * dg],     phf[kc], vhf[0], vhf[1]);
                MMA16816(oacc[2 * dg + 1], phf[kc], vhf[2], vhf[3]);
                MMA16816(oacc[2 * dg],     plf[kc], vhf[0], vhf[1]);
                MMA16816(oacc[2 * dg + 1], plf[kc], vhf[2], vhf[3]);
                MMA16816(oacc[2 * dg],     phf[kc], vlf[0], vlf[1]);
                MMA16816(oacc[2 * dg + 1], phf[kc], vlf[2], vlf[3]);
            }
        }
        __syncthreads();
    }

    float inv0 = 1.f / l0, inv1 = 1.f / l1;
    int row0 = q0 + wid * 16 + gr;
    size_t base0 = ((size_t)b * NW + row0) * DM + h * DK;
    #pragma unroll
    for (int j = 0; j < 8; j++) {
        int d = 8 * j + 2 * c;
        float v0 = oacc[j][0] * inv0, v1 = oacc[j][1] * inv0;
        uint32_t hp, lp;
        PACK_BF16X2(hp, v0, v1);
        float f0 = __uint_as_float(hp << 16), f1 = __uint_as_float(hp & 0xffff0000u);
        PACK_BF16X2(lp, v0 - f0, v1 - f1);
        *(uint32_t*)((__nv_bfloat16*)g_xh + base0 + d) = hp;
        *(uint32_t*)((__nv_bfloat16*)g_xl + base0 + d) = lp;
        v0 = oacc[j][2] * inv1; v1 = oacc[j][3] * inv1;
        PACK_BF16X2(hp, v0, v1);
        f0 = __uint_as_float(hp << 16); f1 = __uint_as_float(hp & 0xffff0000u);
        PACK_BF16X2(lp, v0 - f0, v1 - f1);
        *(uint32_t*)((__nv_bfloat16*)g_xh + base0 + 8 * DM + d) = hp;
        *(uint32_t*)((__nv_bfloat16*)g_xl + base0 + 8 * DM + d) = lp;
    }
}

// ============================================================
extern "C" void kernel_launch(void* const* d_in, const int* in_sizes, int n_in,
                              void* d_out, int out_size) {
    const float* Q  = (const float*)d_in[0];
    const float* K  = (const float*)d_in[1];
    const float* V  = (const float*)d_in[2];
    const int* mask = (const int*)d_in[3];
    const float* Wq = (const float*)d_in[4];
    const float* Wk = (const float*)d_in[5];
    const float* Wv = (const float*)d_in[6];
    const float* Wo = (const float*)d_in[7];
    float* out = (float*)d_out;

    static int attr_done = 0;
    if (!attr_done) {
        cudaFuncSetAttribute(proj_mma_kernel, cudaFuncAttributeMaxDynamicSharedMemorySize, SMEM_MMA);
        cudaFuncSetAttribute(out_mma_kernel, cudaFuncAttributeMaxDynamicSharedMemorySize, SMEM_MMA);
        cudaFuncSetAttribute(flash_mma_kernel, cudaFuncAttributeMaxDynamicSharedMemorySize, SMEM_FLASH);
        attr_done = 1;
    }

    prep_kernel<<<PREP_BLKS, 256>>>(mask, Q, K, V, Wq, Wk, Wv, Wo);
    proj_mma_kernel<<<dim3(DM / 128, MT / 128, 3), 256, SMEM_MMA>>>();
    flash_mma_kernel<<<dim3(NW / 128, NH, NB), 256, SMEM_FLASH>>>();
    out_mma_kernel<<<dim3(DM / 128, MT / 128), 256, SMEM_MMA>>>(out);
}